// round 5
// baseline (speedup 1.0000x reference)
#include <cuda_runtime.h>
#include <math.h>

// Problem-shape constants (N=50000, E=1600000, D=64, H=2)
#define NN 50000
#define EE 1600000
#define DD 64
#define HDIM 128   // H*D

// ---------------- scratch (device globals; no allocation allowed) ----------
__device__ float  g_h2[NN * HDIM];      // interleaved: [n][2*d+hh] = h[n][hh*64+d]
__device__ float  g_adot_i[NN * 2];     // <h[n,h,:], att_i[h]>
__device__ float  g_adot_j[NN * 2];     // <h[n,h,:], att_j[h]>
__device__ float  g_alpha[EE * 2];      // ea = exp(logit)      [E,2]
__device__ float  g_s[NN * 2];          // segment sum of ea (over src)
__device__ float  g_ebdot[30];          // <bond_emb[f,v,h,:], att_j[h]>
__device__ float  g_bsum2[125 * HDIM];  // combined bond table, interleaved, 64KB
__device__ int    g_cnt[NN];            // in-degree histogram (by col/dst)
__device__ int    g_base[NN];           // exclusive scan of cnt
__device__ int    g_cursor[NN];         // atomic cursors for perm
__device__ float4 g_rec[EE];            // sorted-by-dst records {row, w0, w1, code}

__device__ __forceinline__ void red_add_v2(float* p, float a, float b) {
    asm volatile("red.global.add.v2.f32 [%0], {%1,%2};"
                 :: "l"(p), "f"(a), "f"(b) : "memory");
}

// ---------------- K0: zero s/cnt; compute ebdot table ----------------------
__global__ void k_init(const float* __restrict__ att, const float* __restrict__ bond_emb,
                       int N) {
    int i = blockIdx.x * blockDim.x + threadIdx.x;
    if (i < N * 2) g_s[i] = 0.0f;
    if (i < N) g_cnt[i] = 0;
    // ebdot[f*10+v*2+h] = sum_d bond_emb[f,v,h*64+d] * att[h,64+d]
    if (blockIdx.x == 0 && threadIdx.x < 30) {
        int idx = threadIdx.x;
        int f = idx / 10;
        int v = (idx / 2) % 5;
        int hh = idx & 1;
        const float* emb = bond_emb + (f * 5 + v) * HDIM + hh * DD;
        const float* aj  = att + hh * HDIM + DD;
        float acc = 0.0f;
        #pragma unroll 8
        for (int d = 0; d < DD; d++) acc += emb[d] * aj[d];
        g_ebdot[idx] = acc;
    }
}

// ---------------- K0b: combined bond table over 125 codes (interleaved) ----
__global__ void k_bsum(const float* __restrict__ bond_emb) {
    int code = blockIdx.x;          // a0*25 + a1*5 + a2
    int t = threadIdx.x;            // 0..127 : d = t>>1, hh = t&1
    int d = t >> 1, hh = t & 1;
    int a0 = code / 25, a1 = (code / 5) % 5, a2 = code % 5;
    int src = hh * DD + d;
    g_bsum2[code * HDIM + t] = bond_emb[(0 * 5 + a0) * HDIM + src]
                             + bond_emb[(1 * 5 + a1) * HDIM + src]
                             + bond_emb[(2 * 5 + a2) * HDIM + src];
}

// ---------------- K1: h = x@W + b_W, fused per-node attention dots ---------
// 128 threads; thread t owns output column t (W column in regs); 16 nodes/block.
// Writes h head-interleaved; computes adot_i/adot_j via shfl+smem reduce.
__global__ void __launch_bounds__(128) k_gemm(const float* __restrict__ x,
                                              const float* __restrict__ W,
                                              const float* __restrict__ bW,
                                              const float* __restrict__ att, int N) {
    __shared__ float4 xs[16][16];           // 16 nodes x 64 floats
    __shared__ float sAi[4][16], sAj[4][16];
    int t = threadIdx.x;
    int warp = t >> 5, lane = t & 31;
    int hh = t >> 6, d = t & 63;
    float wc[DD];
    #pragma unroll
    for (int k = 0; k < DD; k++) wc[k] = W[k * HDIM + t];
    float b = bW[t];
    float cai = att[hh * HDIM + d];
    float caj = att[hh * HDIM + DD + d];
    int n0 = blockIdx.x * 16;

    for (int i = t; i < 16 * 16; i += 128) {
        int node = n0 + (i >> 4);
        xs[i >> 4][i & 15] = (node < N) ? reinterpret_cast<const float4*>(x)[node * 16 + (i & 15)]
                                        : make_float4(0.f, 0.f, 0.f, 0.f);
    }
    __syncthreads();

    #pragma unroll 4
    for (int i = 0; i < 16; i++) {
        int node = n0 + i;
        if (node >= N) break;
        float acc = b;
        #pragma unroll
        for (int k4 = 0; k4 < 16; k4++) {
            float4 xv = xs[i][k4];
            acc += xv.x * wc[k4 * 4 + 0];
            acc += xv.y * wc[k4 * 4 + 1];
            acc += xv.z * wc[k4 * 4 + 2];
            acc += xv.w * wc[k4 * 4 + 3];
        }
        g_h2[node * HDIM + (d << 1) + hh] = acc;
        float ai = acc * cai;
        float aj = acc * caj;
        #pragma unroll
        for (int o = 16; o > 0; o >>= 1) {
            ai += __shfl_down_sync(0xffffffffu, ai, o);
            aj += __shfl_down_sync(0xffffffffu, aj, o);
        }
        if (lane == 0) { sAi[warp][i] = ai; sAj[warp][i] = aj; }
    }
    __syncthreads();
    if (t < 32) {
        int ni = t & 15, hd = t >> 4;
        int node = n0 + ni;
        if (node < N) {
            g_adot_i[node * 2 + hd] = sAi[2 * hd][ni] + sAi[2 * hd + 1][ni];
            g_adot_j[node * 2 + hd] = sAj[2 * hd][ni] + sAj[2 * hd + 1][ni];
        }
    }
}

// ---------------- K2: fused logits + leaky relu + exp + segsum + hist ------
__global__ void k_softmax(const int* __restrict__ ei, const int* __restrict__ eattr, int E) {
    __shared__ float seb[30];
    if (threadIdx.x < 30) seb[threadIdx.x] = g_ebdot[threadIdx.x];
    __syncthreads();
    int e = blockIdx.x * blockDim.x + threadIdx.x;
    if (e >= E) return;
    int row = ei[e];
    int col = ei[E + e];
    int a0 = eattr[e * 3 + 0], a1 = eattr[e * 3 + 1], a2 = eattr[e * 3 + 2];
    float2 di = reinterpret_cast<const float2*>(g_adot_i)[col];
    float2 dj = reinterpret_cast<const float2*>(g_adot_j)[row];
    float al0 = di.x + dj.x + seb[a0 * 2]     + seb[10 + a1 * 2]     + seb[20 + a2 * 2];
    float al1 = di.y + dj.y + seb[a0 * 2 + 1] + seb[10 + a1 * 2 + 1] + seb[20 + a2 * 2 + 1];
    al0 = (al0 >= 0.f) ? al0 : 0.2f * al0;
    al1 = (al1 >= 0.f) ? al1 : 0.2f * al1;
    float e0 = __expf(al0);
    float e1 = __expf(al1);
    reinterpret_cast<float2*>(g_alpha)[e] = make_float2(e0, e1);
    red_add_v2(&g_s[row * 2], e0, e1);
    atomicAdd(&g_cnt[col], 1);
}

// ---------------- K3: exclusive scan of cnt (single block) ------------------
__global__ void __launch_bounds__(1024) k_scan(int N) {
    __shared__ int ssum[1024];
    int tid = threadIdx.x;
    const int CH = (NN + 1023) / 1024;   // 49
    int beg = tid * CH;
    int s = 0;
    for (int k = 0; k < CH; k++) {
        int i = beg + k;
        if (i < N) s += g_cnt[i];
    }
    ssum[tid] = s;
    __syncthreads();
    for (int off = 1; off < 1024; off <<= 1) {
        int v = (tid >= off) ? ssum[tid - off] : 0;
        __syncthreads();
        ssum[tid] += v;
        __syncthreads();
    }
    int run = ssum[tid] - s;   // exclusive prefix for this thread's chunk
    for (int k = 0; k < CH; k++) {
        int i = beg + k;
        if (i < N) {
            g_base[i] = run;
            g_cursor[i] = run;
            run += g_cnt[i];
        }
    }
}

// ---------------- K4: build sorted-by-dst packed records -------------------
__global__ void k_perm(const int* __restrict__ ei, const int* __restrict__ eattr, int E) {
    int e = blockIdx.x * blockDim.x + threadIdx.x;
    if (e >= E) return;
    int row = ei[e];
    int col = ei[E + e];
    float2 ea = reinterpret_cast<const float2*>(g_alpha)[e];
    float2 s2 = reinterpret_cast<const float2*>(g_s)[row];
    float w0 = 0.5f * __fdividef(ea.x, s2.x + 1e-16f);
    float w1 = 0.5f * __fdividef(ea.y, s2.y + 1e-16f);
    int code = eattr[e * 3 + 0] * 25 + eattr[e * 3 + 1] * 5 + eattr[e * 3 + 2];
    int pos = atomicAdd(&g_cursor[col], 1);
    g_rec[pos] = make_float4(__int_as_float(row), w0, w1, __int_as_float(code));
}

// ---------------- K5: per-dst aggregation, no output atomics ---------------
// One warp per dst node (grid-stride). Records read 32-at-a-time (LDG.128
// coalesced) then shfl-broadcast. Lane owns output dims {lane, lane+32}.
__global__ void __launch_bounds__(256) k_aggr(const float* __restrict__ bias,
                                              float* __restrict__ out, int N) {
    extern __shared__ float sb[];   // 125*128 floats = 64000B, interleaved
    int t = threadIdx.x;
    for (int i = t; i < 125 * 32; i += 256)
        reinterpret_cast<float4*>(sb)[i] = reinterpret_cast<const float4*>(g_bsum2)[i];
    __syncthreads();

    int lane = t & 31;
    int gw = blockIdx.x * 8 + (t >> 5);
    int nw = gridDim.x * 8;
    float bias0 = bias[lane], bias1 = bias[lane + 32];

    for (int n = gw; n < N; n += nw) {
        int beg = g_base[n];
        int deg = g_cnt[n];
        float acc0 = 0.f, acc1 = 0.f;
        for (int k0 = 0; k0 < deg; k0 += 32) {
            float4 r = make_float4(0.f, 0.f, 0.f, 0.f);
            if (k0 + lane < deg) r = g_rec[beg + k0 + lane];
            int nb = min(32, deg - k0);
            if (nb == 32) {
                #pragma unroll 8
                for (int k = 0; k < 32; k++) {
                    int   row  = __shfl_sync(0xffffffffu, __float_as_int(r.x), k);
                    float w0   = __shfl_sync(0xffffffffu, r.y, k);
                    float w1   = __shfl_sync(0xffffffffu, r.z, k);
                    int   code = __shfl_sync(0xffffffffu, __float_as_int(r.w), k);
                    const float2* hp = reinterpret_cast<const float2*>(g_h2 + row * HDIM);
                    float2 hA = hp[lane];
                    float2 hB = hp[32 + lane];
                    const float2* bp = reinterpret_cast<const float2*>(sb + code * HDIM);
                    float2 bA = bp[lane];
                    float2 bB = bp[32 + lane];
                    acc0 += w0 * (hA.x + bA.x) + w1 * (hA.y + bA.y);
                    acc1 += w0 * (hB.x + bB.x) + w1 * (hB.y + bB.y);
                }
            } else {
                for (int k = 0; k < nb; k++) {
                    int   row  = __shfl_sync(0xffffffffu, __float_as_int(r.x), k);
                    float w0   = __shfl_sync(0xffffffffu, r.y, k);
                    float w1   = __shfl_sync(0xffffffffu, r.z, k);
                    int   code = __shfl_sync(0xffffffffu, __float_as_int(r.w), k);
                    const float2* hp = reinterpret_cast<const float2*>(g_h2 + row * HDIM);
                    float2 hA = hp[lane];
                    float2 hB = hp[32 + lane];
                    const float2* bp = reinterpret_cast<const float2*>(sb + code * HDIM);
                    float2 bA = bp[lane];
                    float2 bB = bp[32 + lane];
                    acc0 += w0 * (hA.x + bA.x) + w1 * (hA.y + bA.y);
                    acc1 += w0 * (hB.x + bB.x) + w1 * (hB.y + bB.y);
                }
            }
        }
        out[n * DD + lane]      = acc0 + bias0;
        out[n * DD + 32 + lane] = acc1 + bias1;
    }
}

// ---------------- launch ----------------------------------------------------
extern "C" void kernel_launch(void* const* d_in, const int* in_sizes, int n_in,
                              void* d_out, int out_size) {
    const float* x        = (const float*)d_in[0];
    const int*   ei       = (const int*)  d_in[1];
    const int*   eattr    = (const int*)  d_in[2];
    const float* W        = (const float*)d_in[3];
    const float* bW       = (const float*)d_in[4];
    const float* att      = (const float*)d_in[5];
    const float* bias     = (const float*)d_in[6];
    const float* bond_emb = (const float*)d_in[7];
    float* out = (float*)d_out;

    int N = in_sizes[0] / DD;
    int E = in_sizes[1] / 2;

    static bool attr_set = false;
    if (!attr_set) {
        cudaFuncSetAttribute(k_aggr, cudaFuncAttributeMaxDynamicSharedMemorySize, 64000);
        attr_set = true;
    }

    // K0: zero s/cnt, ebdot table
    {
        int grid = (N * 2 + 255) / 256;
        k_init<<<grid, 256>>>(att, bond_emb, N);
    }
    // K0b: combined bond table (interleaved)
    k_bsum<<<125, 128>>>(bond_emb);
    // K1: h (interleaved) + per-node attention dots, fused
    {
        int grid = (N + 15) / 16;
        k_gemm<<<grid, 128>>>(x, W, bW, att, N);
    }
    // K2: softmax numerator + segment sum + dst histogram
    {
        int grid = (E + 255) / 256;
        k_softmax<<<grid, 256>>>(ei, eattr, E);
    }
    // K3: exclusive scan
    k_scan<<<1, 1024>>>(N);
    // K4: sorted packed records
    {
        int grid = (E + 255) / 256;
        k_perm<<<grid, 256>>>(ei, eattr, E);
    }
    // K5: per-dst register aggregation
    k_aggr<<<444, 256, 64000>>>(bias, out, N);
}

// round 6
// speedup vs baseline: 1.1822x; 1.1822x over previous
#include <cuda_runtime.h>
#include <cuda_fp16.h>
#include <math.h>

// Problem-shape constants (N=50000, E=1600000, D=64, H=2)
#define NN 50000
#define EE 1600000
#define DD 64
#define HDIM 128   // H*D

// ---------------- scratch (device globals; no allocation allowed) ----------
__device__ float    g_adot_i[NN * 2];   // <h[n,h,:], att_i[h]>  (via x-space dots)
__device__ float    g_adot_j[NN * 2];
__device__ float    g_s[NN * 2];        // segment sum of exp(alpha) over src
__device__ float    g_sinv[NN * 2];     // 0.5/(s+1e-16)
__device__ float    g_ebdot[30];        // <bond_emb[f,v,h,:], att_j[h]>
__device__ float    g_u[4 * DD];        // [ui_h0, ui_h1, uj_h0, uj_h1] 64-vecs
__device__ float    g_c[4];             // ci0, ci1, cj0, cj1 (bW dot att)
__device__ unsigned g_bsumh[125 * DD];  // half2 per (code,d): (bond'[h0,d], bond'[h1,d])
__device__ int      g_cnt[NN];          // in-degree (by col/dst)
__device__ int      g_base[NN];         // exclusive scan
__device__ int      g_cursor[NN];       // atomic cursors
__device__ float4   g_rec[EE];          // sorted-by-dst: {row|code<<17, e0, e1, 0}
__device__ float    g_z[NN * HDIM];     // weighted x sums  [n][h*64+d]

__device__ __forceinline__ void red_add_v2(float* p, float a, float b) {
    asm volatile("red.global.add.v2.f32 [%0], {%1,%2};"
                 :: "l"(p), "f"(a), "f"(b) : "memory");
}

// ---------------- K0: zero s / cnt ------------------------------------------
__global__ void k_init(int N) {
    int i = blockIdx.x * blockDim.x + threadIdx.x;
    if (i < N * 2) g_s[i] = 0.0f;
    if (i < N) g_cnt[i] = 0;
}

// ---------------- K1: precompute tables -------------------------------------
// Blocks 0..124: half2 bond' table (3-feature sum + bW folded), per code.
// Block 125: u_i/u_j vectors (W projected onto att halves), ebdot, c consts.
__global__ void k_prep(const float* __restrict__ W, const float* __restrict__ bW,
                       const float* __restrict__ att, const float* __restrict__ bond_emb) {
    int bid = blockIdx.x;
    int t = threadIdx.x;
    if (bid < 125) {
        if (t < DD) {   // d = t; pack (h0,h1) halves
            int a0 = bid / 25, a1 = (bid / 5) % 5, a2 = bid % 5;
            float v0 = bond_emb[(0 * 5 + a0) * HDIM + t]
                     + bond_emb[(1 * 5 + a1) * HDIM + t]
                     + bond_emb[(2 * 5 + a2) * HDIM + t] + bW[t];
            float v1 = bond_emb[(0 * 5 + a0) * HDIM + DD + t]
                     + bond_emb[(1 * 5 + a1) * HDIM + DD + t]
                     + bond_emb[(2 * 5 + a2) * HDIM + DD + t] + bW[DD + t];
            __half2 hv = __float22half2_rn(make_float2(v0, v1));
            g_bsumh[bid * DD + t] = *reinterpret_cast<unsigned*>(&hv);
        }
        return;
    }
    // block 125
    if (t < 128) {       // u vectors: (hh, d)
        int hh = t >> 6, d = t & 63;
        const float* wr = W + d * HDIM + hh * DD;
        const float* ai = att + hh * HDIM;
        const float* aj = att + hh * HDIM + DD;
        float ui = 0.f, uj = 0.f;
        #pragma unroll 8
        for (int k = 0; k < DD; k++) { ui += wr[k] * ai[k]; uj += wr[k] * aj[k]; }
        g_u[hh * DD + d] = ui;
        g_u[128 + hh * DD + d] = uj;
    } else if (t < 158) {  // ebdot
        int idx = t - 128;
        int f = idx / 10, v = (idx / 2) % 5, hh = idx & 1;
        const float* emb = bond_emb + (f * 5 + v) * HDIM + hh * DD;
        const float* aj  = att + hh * HDIM + DD;
        float acc = 0.0f;
        #pragma unroll 8
        for (int d = 0; d < DD; d++) acc += emb[d] * aj[d];
        g_ebdot[idx] = acc;
    } else if (t == 158) { // bW consts
        for (int hh = 0; hh < 2; hh++) {
            float ci = 0.f, cj = 0.f;
            for (int d = 0; d < DD; d++) {
                float b = bW[hh * DD + d];
                ci += b * att[hh * HDIM + d];
                cj += b * att[hh * HDIM + DD + d];
            }
            g_c[hh] = ci;
            g_c[2 + hh] = cj;
        }
    }
}

// ---------------- K2: per-node attention dots (x-space) + dst histogram ----
// grid 6250 x 256: warp w handles node bid*8+w; thread t handles edge bid*256+t.
__global__ void __launch_bounds__(256) k_adot_hist(const float* __restrict__ x,
                                                   const int* __restrict__ ei,
                                                   int N, int E) {
    __shared__ float su[256];
    int t = threadIdx.x;
    su[t] = g_u[t];
    __syncthreads();

    int e = blockIdx.x * 256 + t;
    if (e < E) atomicAdd(&g_cnt[ei[E + e]], 1);

    int lane = t & 31;
    int n = blockIdx.x * 8 + (t >> 5);
    if (n >= N) return;
    float2 xv = reinterpret_cast<const float2*>(x)[n * 32 + lane];  // d=2lane,2lane+1
    float ai0 = xv.x * su[2 * lane]          + xv.y * su[2 * lane + 1];
    float ai1 = xv.x * su[64 + 2 * lane]     + xv.y * su[64 + 2 * lane + 1];
    float aj0 = xv.x * su[128 + 2 * lane]    + xv.y * su[128 + 2 * lane + 1];
    float aj1 = xv.x * su[192 + 2 * lane]    + xv.y * su[192 + 2 * lane + 1];
    #pragma unroll
    for (int o = 16; o > 0; o >>= 1) {
        ai0 += __shfl_down_sync(0xffffffffu, ai0, o);
        ai1 += __shfl_down_sync(0xffffffffu, ai1, o);
        aj0 += __shfl_down_sync(0xffffffffu, aj0, o);
        aj1 += __shfl_down_sync(0xffffffffu, aj1, o);
    }
    if (lane == 0) {
        reinterpret_cast<float2*>(g_adot_i)[n] = make_float2(ai0 + g_c[0], ai1 + g_c[1]);
        reinterpret_cast<float2*>(g_adot_j)[n] = make_float2(aj0 + g_c[2], aj1 + g_c[3]);
    }
}

// ---------------- K3: exclusive scan of cnt (single block) ------------------
__global__ void __launch_bounds__(1024) k_scan(int N) {
    __shared__ int ssum[1024];
    int tid = threadIdx.x;
    const int CH = (NN + 1023) / 1024;   // 49
    int beg = tid * CH;
    int s = 0;
    for (int k = 0; k < CH; k++) {
        int i = beg + k;
        if (i < N) s += g_cnt[i];
    }
    ssum[tid] = s;
    __syncthreads();
    for (int off = 1; off < 1024; off <<= 1) {
        int v = (tid >= off) ? ssum[tid - off] : 0;
        __syncthreads();
        ssum[tid] += v;
        __syncthreads();
    }
    int run = ssum[tid] - s;
    for (int k = 0; k < CH; k++) {
        int i = beg + k;
        if (i < N) {
            g_base[i] = run;
            g_cursor[i] = run;
            run += g_cnt[i];
        }
    }
}

// ---------------- K4: fused logits+leakyrelu+exp+segsum+perm ---------------
__global__ void k_softperm(const int* __restrict__ ei, const int* __restrict__ eattr, int E) {
    __shared__ float seb[30];
    if (threadIdx.x < 30) seb[threadIdx.x] = g_ebdot[threadIdx.x];
    __syncthreads();
    int e = blockIdx.x * blockDim.x + threadIdx.x;
    if (e >= E) return;
    int row = ei[e];
    int col = ei[E + e];
    int a0 = eattr[e * 3 + 0], a1 = eattr[e * 3 + 1], a2 = eattr[e * 3 + 2];
    float2 di = reinterpret_cast<const float2*>(g_adot_i)[col];
    float2 dj = reinterpret_cast<const float2*>(g_adot_j)[row];
    float al0 = di.x + dj.x + seb[a0 * 2]     + seb[10 + a1 * 2]     + seb[20 + a2 * 2];
    float al1 = di.y + dj.y + seb[a0 * 2 + 1] + seb[10 + a1 * 2 + 1] + seb[20 + a2 * 2 + 1];
    al0 = (al0 >= 0.f) ? al0 : 0.2f * al0;
    al1 = (al1 >= 0.f) ? al1 : 0.2f * al1;
    float e0 = __expf(al0);
    float e1 = __expf(al1);
    red_add_v2(&g_s[row * 2], e0, e1);
    int code = a0 * 25 + a1 * 5 + a2;
    int packed = row | (code << 17);
    int pos = atomicAdd(&g_cursor[col], 1);
    g_rec[pos] = make_float4(__int_as_float(packed), e0, e1, 0.f);
}

// ---------------- K5: sinv = 0.5/(s+eps) ------------------------------------
__global__ void k_sinv(int N) {
    int i = blockIdx.x * blockDim.x + threadIdx.x;
    if (i < N * 2) g_sinv[i] = __fdividef(0.5f, g_s[i] + 1e-16f);
}

// ---------------- K6: per-dst aggregation of x (no atomics) -----------------
// Warp per dst node. Lane owns dims {lane, lane+32}. Accumulates weighted x
// into z[n][h*64+d] and bond contribution (half2 table in 32KB smem) into out.
#define AGGR_BODY(KK)                                                              \
    {                                                                              \
        int pk = __shfl_sync(0xffffffffu, pkl, KK);                                \
        float w0 = __shfl_sync(0xffffffffu, w0l, KK);                              \
        float w1 = __shfl_sync(0xffffffffu, w1l, KK);                              \
        int row = pk & 0x1FFFF;                                                    \
        int code = pk >> 17;                                                       \
        float xa = __ldg(x + row * DD + lane);                                     \
        float xb = __ldg(x + row * DD + 32 + lane);                                \
        z0a += w0 * xa; z1a += w1 * xa;                                            \
        z0b += w0 * xb; z1b += w1 * xb;                                            \
        unsigned ua = sb[code * DD + lane];                                        \
        unsigned ub = sb[code * DD + 32 + lane];                                   \
        float2 fa = __half22float2(*reinterpret_cast<__half2*>(&ua));              \
        float2 fb = __half22float2(*reinterpret_cast<__half2*>(&ub));              \
        ba += w0 * fa.x + w1 * fa.y;                                               \
        bb += w0 * fb.x + w1 * fb.y;                                               \
    }

__global__ void __launch_bounds__(256) k_aggr(const float* __restrict__ x,
                                              float* __restrict__ out, int N) {
    __shared__ unsigned sb[125 * DD];   // 32000 B
    int t = threadIdx.x;
    for (int i = t; i < 125 * DD; i += 256) sb[i] = g_bsumh[i];
    __syncthreads();

    int lane = t & 31;
    int gw = blockIdx.x * 8 + (t >> 5);
    int nw = gridDim.x * 8;

    for (int n = gw; n < N; n += nw) {
        int beg = g_base[n];
        int deg = g_cnt[n];
        float z0a = 0.f, z0b = 0.f, z1a = 0.f, z1b = 0.f, ba = 0.f, bb = 0.f;
        for (int k0 = 0; k0 < deg; k0 += 32) {
            int nb = min(32, deg - k0);
            float4 r = make_float4(0.f, 0.f, 0.f, 0.f);
            float2 si = make_float2(0.f, 0.f);
            int pkl = 0;
            if (lane < nb) {
                r = g_rec[beg + k0 + lane];
                pkl = __float_as_int(r.x);
                si = reinterpret_cast<const float2*>(g_sinv)[pkl & 0x1FFFF];
            }
            float w0l = r.y * si.x;
            float w1l = r.z * si.y;
            if (nb == 32) {
                #pragma unroll 8
                for (int k = 0; k < 32; k++) AGGR_BODY(k)
            } else {
                for (int k = 0; k < nb; k++) AGGR_BODY(k)
            }
        }
        g_z[n * HDIM + lane]      = z0a;
        g_z[n * HDIM + 32 + lane] = z0b;
        g_z[n * HDIM + 64 + lane] = z1a;
        g_z[n * HDIM + 96 + lane] = z1b;
        out[n * DD + lane]      = ba;    // bond part; zgemm adds the rest
        out[n * DD + 32 + lane] = bb;
    }
}

// ---------------- K7: out += z @ W (head-structured) + bias ----------------
// 128 threads: (hh = t>>6, dp = t&63) computes partial_h[n][dp]; combine via smem.
__global__ void __launch_bounds__(128) k_zgemm(const float* __restrict__ W,
                                               const float* __restrict__ bias,
                                               float* __restrict__ out, int N) {
    __shared__ float4 sz[16 * 32];      // 16 nodes x 128 floats
    __shared__ float sp[16][128];
    int t = threadIdx.x;
    int hh = t >> 6, dp = t & 63;
    float wcol[DD];
    #pragma unroll
    for (int d = 0; d < DD; d++) wcol[d] = W[d * HDIM + hh * DD + dp];

    int n0 = blockIdx.x * 16;
    for (int i = t; i < 16 * 32; i += 128) {
        int node = n0 + (i >> 5);
        sz[i] = (node < N) ? reinterpret_cast<const float4*>(g_z)[node * 32 + (i & 31)]
                           : make_float4(0.f, 0.f, 0.f, 0.f);
    }
    __syncthreads();

    #pragma unroll 2
    for (int i = 0; i < 16; i++) {
        const float4* zr = sz + i * 32 + hh * 16;
        float acc = 0.f;
        #pragma unroll
        for (int d4 = 0; d4 < 16; d4++) {
            float4 zv = zr[d4];
            acc += zv.x * wcol[d4 * 4 + 0];
            acc += zv.y * wcol[d4 * 4 + 1];
            acc += zv.z * wcol[d4 * 4 + 2];
            acc += zv.w * wcol[d4 * 4 + 3];
        }
        sp[i][t] = acc;
    }
    __syncthreads();

    #pragma unroll
    for (int rep = 0; rep < 8; rep++) {
        int o = rep * 128 + t;            // 0..1023
        int i = o >> 6, dpp = o & 63;
        int node = n0 + i;
        if (node < N) {
            int idx = node * DD + dpp;
            out[idx] = out[idx] + sp[i][dpp] + sp[i][64 + dpp] + bias[dpp];
        }
    }
}

// ---------------- launch ----------------------------------------------------
extern "C" void kernel_launch(void* const* d_in, const int* in_sizes, int n_in,
                              void* d_out, int out_size) {
    const float* x        = (const float*)d_in[0];
    const int*   ei       = (const int*)  d_in[1];
    const int*   eattr    = (const int*)  d_in[2];
    const float* W        = (const float*)d_in[3];
    const float* bW       = (const float*)d_in[4];
    const float* att      = (const float*)d_in[5];
    const float* bias     = (const float*)d_in[6];
    const float* bond_emb = (const float*)d_in[7];
    float* out = (float*)d_out;

    int N = in_sizes[0] / DD;
    int E = in_sizes[1] / 2;

    k_init<<<(N * 2 + 255) / 256, 256>>>(N);
    k_prep<<<126, 256>>>(W, bW, att, bond_emb);
    k_adot_hist<<<(E + 255) / 256, 256>>>(x, ei, N, E);
    k_scan<<<1, 1024>>>(N);
    k_softperm<<<(E + 255) / 256, 256>>>(ei, eattr, E);
    k_sinv<<<(N * 2 + 255) / 256, 256>>>(N);
    k_aggr<<<888, 256>>>(x, out, N);
    k_zgemm<<<(N + 15) / 16, 128>>>(W, bias, out, N);
}

// round 7
// speedup vs baseline: 1.6030x; 1.3560x over previous
#include <cuda_runtime.h>
#include <cuda_fp16.h>
#include <math.h>

// Problem-shape constants (N=50000, E=1600000, D=64, H=2)
#define NN 50000
#define EE 1600000
#define DD 64
#define HDIM 128   // H*D

#define SCAN_BLOCKS 49   // ceil(50000/1024)

// ---------------- scratch (device globals; no allocation allowed) ----------
__device__ float    g_adot_i[NN * 2];   // <h[n,h,:], att_i[h]>  (via x-space dots)
__device__ float    g_adot_j[NN * 2];
__device__ float    g_s[NN * 2];        // segment sum of exp(alpha) over src
__device__ float    g_sinv[NN * 2];     // 0.5/(s+1e-16)
__device__ float    g_ebdot[30];        // <bond_emb[f,v,h,:], att_j[h]>
__device__ float    g_u[4 * DD];        // [ui_h0, ui_h1, uj_h0, uj_h1] 64-vecs
__device__ float    g_c[4];             // ci0, ci1, cj0, cj1 (bW dot att)
__device__ unsigned g_bsumh[125 * DD];  // half2 per (code,d): (bond'[h0,d], bond'[h1,d])
__device__ int      g_cnt[NN];          // in-degree (by col/dst)
__device__ int      g_base[NN];         // exclusive scan
__device__ int      g_cursor[NN];       // atomic cursors
__device__ int      g_part[64];         // scan partials
__device__ float4   g_rec[EE];          // sorted-by-dst: {row|code<<17, e0, e1, 0}
__device__ float    g_z[NN * HDIM];     // weighted x sums  [n][h*64+d]

__device__ __forceinline__ void red_add_v2(float* p, float a, float b) {
    asm volatile("red.global.add.v2.f32 [%0], {%1,%2};"
                 :: "l"(p), "f"(a), "f"(b) : "memory");
}

// ---------------- K0: zero s / cnt ------------------------------------------
__global__ void k_init(int N) {
    int i = blockIdx.x * blockDim.x + threadIdx.x;
    if (i < N * 2) g_s[i] = 0.0f;
    if (i < N) g_cnt[i] = 0;
}

// ---------------- K1: precompute tables -------------------------------------
__global__ void k_prep(const float* __restrict__ W, const float* __restrict__ bW,
                       const float* __restrict__ att, const float* __restrict__ bond_emb) {
    int bid = blockIdx.x;
    int t = threadIdx.x;
    if (bid < 125) {
        if (t < DD) {   // d = t; pack (h0,h1) halves + fold bW
            int a0 = bid / 25, a1 = (bid / 5) % 5, a2 = bid % 5;
            float v0 = bond_emb[(0 * 5 + a0) * HDIM + t]
                     + bond_emb[(1 * 5 + a1) * HDIM + t]
                     + bond_emb[(2 * 5 + a2) * HDIM + t] + bW[t];
            float v1 = bond_emb[(0 * 5 + a0) * HDIM + DD + t]
                     + bond_emb[(1 * 5 + a1) * HDIM + DD + t]
                     + bond_emb[(2 * 5 + a2) * HDIM + DD + t] + bW[DD + t];
            __half2 hv = __float22half2_rn(make_float2(v0, v1));
            g_bsumh[bid * DD + t] = *reinterpret_cast<unsigned*>(&hv);
        }
        return;
    }
    // block 125
    if (t < 128) {       // u vectors: (hh, d)
        int hh = t >> 6, d = t & 63;
        const float* wr = W + d * HDIM + hh * DD;
        const float* ai = att + hh * HDIM;
        const float* aj = att + hh * HDIM + DD;
        float ui = 0.f, uj = 0.f;
        #pragma unroll 8
        for (int k = 0; k < DD; k++) { ui += wr[k] * ai[k]; uj += wr[k] * aj[k]; }
        g_u[hh * DD + d] = ui;
        g_u[128 + hh * DD + d] = uj;
    } else if (t < 158) {  // ebdot
        int idx = t - 128;
        int f = idx / 10, v = (idx / 2) % 5, hh = idx & 1;
        const float* emb = bond_emb + (f * 5 + v) * HDIM + hh * DD;
        const float* aj  = att + hh * HDIM + DD;
        float acc = 0.0f;
        #pragma unroll 8
        for (int d = 0; d < DD; d++) acc += emb[d] * aj[d];
        g_ebdot[idx] = acc;
    } else if (t == 158) { // bW consts
        for (int hh = 0; hh < 2; hh++) {
            float ci = 0.f, cj = 0.f;
            for (int d = 0; d < DD; d++) {
                float b = bW[hh * DD + d];
                ci += b * att[hh * HDIM + d];
                cj += b * att[hh * HDIM + DD + d];
            }
            g_c[hh] = ci;
            g_c[2 + hh] = cj;
        }
    }
}

// ---------------- K2: per-node attention dots (x-space) + dst histogram ----
__global__ void __launch_bounds__(256) k_adot_hist(const float* __restrict__ x,
                                                   const int* __restrict__ ei,
                                                   int N, int E) {
    __shared__ float su[256];
    int t = threadIdx.x;
    su[t] = g_u[t];
    __syncthreads();

    int e = blockIdx.x * 256 + t;
    if (e < E) atomicAdd(&g_cnt[ei[E + e]], 1);

    int lane = t & 31;
    int n = blockIdx.x * 8 + (t >> 5);
    if (n >= N) return;
    float2 xv = reinterpret_cast<const float2*>(x)[n * 32 + lane];  // d=2lane,2lane+1
    float ai0 = xv.x * su[2 * lane]          + xv.y * su[2 * lane + 1];
    float ai1 = xv.x * su[64 + 2 * lane]     + xv.y * su[64 + 2 * lane + 1];
    float aj0 = xv.x * su[128 + 2 * lane]    + xv.y * su[128 + 2 * lane + 1];
    float aj1 = xv.x * su[192 + 2 * lane]    + xv.y * su[192 + 2 * lane + 1];
    #pragma unroll
    for (int o = 16; o > 0; o >>= 1) {
        ai0 += __shfl_down_sync(0xffffffffu, ai0, o);
        ai1 += __shfl_down_sync(0xffffffffu, ai1, o);
        aj0 += __shfl_down_sync(0xffffffffu, aj0, o);
        aj1 += __shfl_down_sync(0xffffffffu, aj1, o);
    }
    if (lane == 0) {
        reinterpret_cast<float2*>(g_adot_i)[n] = make_float2(ai0 + g_c[0], ai1 + g_c[1]);
        reinterpret_cast<float2*>(g_adot_j)[n] = make_float2(aj0 + g_c[2], aj1 + g_c[3]);
    }
}

// ---------------- K3: 3-phase coalesced scan of cnt -------------------------
// Phase 1: per-block sums (coalesced)
__global__ void __launch_bounds__(1024) k_scan1(int N) {
    __shared__ int sred[32];
    int t = threadIdx.x;
    int i = blockIdx.x * 1024 + t;
    int v = (i < N) ? g_cnt[i] : 0;
    int s = v;
    #pragma unroll
    for (int o = 16; o > 0; o >>= 1) s += __shfl_down_sync(0xffffffffu, s, o);
    if ((t & 31) == 0) sred[t >> 5] = s;
    __syncthreads();
    if (t < 32) {
        int r = sred[t];
        #pragma unroll
        for (int o = 16; o > 0; o >>= 1) r += __shfl_down_sync(0xffffffffu, r, o);
        if (t == 0) g_part[blockIdx.x] = r;
    }
}

// Phase 2: exclusive scan of block partials (one tiny block)
__global__ void k_scan2() {
    __shared__ int sp[64];
    int t = threadIdx.x;  // 64 threads
    int v = (t < SCAN_BLOCKS) ? g_part[t] : 0;
    sp[t] = v;
    __syncthreads();
    #pragma unroll
    for (int off = 1; off < 64; off <<= 1) {
        int u = (t >= off) ? sp[t - off] : 0;
        __syncthreads();
        sp[t] += u;
        __syncthreads();
    }
    if (t < SCAN_BLOCKS) g_part[t] = sp[t] - v;   // exclusive
}

// Phase 3: per-block inclusive scan + offset; write base & cursor (coalesced)
__global__ void __launch_bounds__(1024) k_scan3(int N) {
    __shared__ int ss[1024];
    int t = threadIdx.x;
    int i = blockIdx.x * 1024 + t;
    int v = (i < N) ? g_cnt[i] : 0;
    ss[t] = v;
    __syncthreads();
    #pragma unroll
    for (int off = 1; off < 1024; off <<= 1) {
        int u = (t >= off) ? ss[t - off] : 0;
        __syncthreads();
        ss[t] += u;
        __syncthreads();
    }
    if (i < N) {
        int excl = ss[t] - v + g_part[blockIdx.x];
        g_base[i] = excl;
        g_cursor[i] = excl;
    }
}

// ---------------- K4: fused logits+leakyrelu+exp+segsum+perm ---------------
__global__ void k_softperm(const int* __restrict__ ei, const int* __restrict__ eattr, int E) {
    __shared__ float seb[30];
    if (threadIdx.x < 30) seb[threadIdx.x] = g_ebdot[threadIdx.x];
    __syncthreads();
    int e = blockIdx.x * blockDim.x + threadIdx.x;
    if (e >= E) return;
    int row = ei[e];
    int col = ei[E + e];
    int a0 = eattr[e * 3 + 0], a1 = eattr[e * 3 + 1], a2 = eattr[e * 3 + 2];
    float2 di = reinterpret_cast<const float2*>(g_adot_i)[col];
    float2 dj = reinterpret_cast<const float2*>(g_adot_j)[row];
    float al0 = di.x + dj.x + seb[a0 * 2]     + seb[10 + a1 * 2]     + seb[20 + a2 * 2];
    float al1 = di.y + dj.y + seb[a0 * 2 + 1] + seb[10 + a1 * 2 + 1] + seb[20 + a2 * 2 + 1];
    al0 = (al0 >= 0.f) ? al0 : 0.2f * al0;
    al1 = (al1 >= 0.f) ? al1 : 0.2f * al1;
    float e0 = __expf(al0);
    float e1 = __expf(al1);
    red_add_v2(&g_s[row * 2], e0, e1);
    int code = a0 * 25 + a1 * 5 + a2;
    int packed = row | (code << 17);
    int pos = atomicAdd(&g_cursor[col], 1);
    g_rec[pos] = make_float4(__int_as_float(packed), e0, e1, 0.f);
}

// ---------------- K5: sinv = 0.5/(s+eps) ------------------------------------
__global__ void k_sinv(int N) {
    int i = blockIdx.x * blockDim.x + threadIdx.x;
    if (i < N * 2) g_sinv[i] = __fdividef(0.5f, g_s[i] + 1e-16f);
}

// ---------------- K6: per-dst aggregation of x (no atomics) -----------------
#define AGGR_BODY(KK)                                                              \
    {                                                                              \
        int pk = __shfl_sync(0xffffffffu, pkl, KK);                                \
        float w0 = __shfl_sync(0xffffffffu, w0l, KK);                              \
        float w1 = __shfl_sync(0xffffffffu, w1l, KK);                              \
        int row = pk & 0x1FFFF;                                                    \
        int code = pk >> 17;                                                       \
        float xa = __ldg(x + row * DD + lane);                                     \
        float xb = __ldg(x + row * DD + 32 + lane);                                \
        z0a += w0 * xa; z1a += w1 * xa;                                            \
        z0b += w0 * xb; z1b += w1 * xb;                                            \
        unsigned ua = sb[code * DD + lane];                                        \
        unsigned ub = sb[code * DD + 32 + lane];                                   \
        float2 fa = __half22float2(*reinterpret_cast<__half2*>(&ua));              \
        float2 fb = __half22float2(*reinterpret_cast<__half2*>(&ub));              \
        ba += w0 * fa.x + w1 * fa.y;                                               \
        bb += w0 * fb.x + w1 * fb.y;                                               \
    }

__global__ void __launch_bounds__(256) k_aggr(const float* __restrict__ x,
                                              float* __restrict__ out, int N) {
    __shared__ unsigned sb[125 * DD];   // 32000 B
    int t = threadIdx.x;
    for (int i = t; i < 125 * DD; i += 256) sb[i] = g_bsumh[i];
    __syncthreads();

    int lane = t & 31;
    int gw = blockIdx.x * 8 + (t >> 5);
    int nw = gridDim.x * 8;

    for (int n = gw; n < N; n += nw) {
        int beg = g_base[n];
        int deg = g_cnt[n];
        float z0a = 0.f, z0b = 0.f, z1a = 0.f, z1b = 0.f, ba = 0.f, bb = 0.f;
        for (int k0 = 0; k0 < deg; k0 += 32) {
            int nb = min(32, deg - k0);
            float4 r = make_float4(0.f, 0.f, 0.f, 0.f);
            float2 si = make_float2(0.f, 0.f);
            int pkl = 0;
            if (lane < nb) {
                r = g_rec[beg + k0 + lane];
                pkl = __float_as_int(r.x);
                si = reinterpret_cast<const float2*>(g_sinv)[pkl & 0x1FFFF];
            }
            float w0l = r.y * si.x;
            float w1l = r.z * si.y;
            if (nb == 32) {
                #pragma unroll 8
                for (int k = 0; k < 32; k++) AGGR_BODY(k)
            } else {
                for (int k = 0; k < nb; k++) AGGR_BODY(k)
            }
        }
        g_z[n * HDIM + lane]      = z0a;
        g_z[n * HDIM + 32 + lane] = z0b;
        g_z[n * HDIM + 64 + lane] = z1a;
        g_z[n * HDIM + 96 + lane] = z1b;
        out[n * DD + lane]      = ba;    // bond part; zgemm adds the rest
        out[n * DD + 32 + lane] = bb;
    }
}

// ---------------- K7: out += z @ W (head-structured) + bias ----------------
__global__ void __launch_bounds__(128) k_zgemm(const float* __restrict__ W,
                                               const float* __restrict__ bias,
                                               float* __restrict__ out, int N) {
    __shared__ float4 sz[16 * 32];      // 16 nodes x 128 floats
    __shared__ float sp[16][128];
    int t = threadIdx.x;
    int hh = t >> 6, dp = t & 63;
    float wcol[DD];
    #pragma unroll
    for (int d = 0; d < DD; d++) wcol[d] = W[d * HDIM + hh * DD + dp];

    int n0 = blockIdx.x * 16;
    for (int i = t; i < 16 * 32; i += 128) {
        int node = n0 + (i >> 5);
        sz[i] = (node < N) ? reinterpret_cast<const float4*>(g_z)[node * 32 + (i & 31)]
                           : make_float4(0.f, 0.f, 0.f, 0.f);
    }
    __syncthreads();

    #pragma unroll 2
    for (int i = 0; i < 16; i++) {
        const float4* zr = sz + i * 32 + hh * 16;
        float acc = 0.f;
        #pragma unroll
        for (int d4 = 0; d4 < 16; d4++) {
            float4 zv = zr[d4];
            acc += zv.x * wcol[d4 * 4 + 0];
            acc += zv.y * wcol[d4 * 4 + 1];
            acc += zv.z * wcol[d4 * 4 + 2];
            acc += zv.w * wcol[d4 * 4 + 3];
        }
        sp[i][t] = acc;
    }
    __syncthreads();

    #pragma unroll
    for (int rep = 0; rep < 8; rep++) {
        int o = rep * 128 + t;            // 0..1023
        int i = o >> 6, dpp = o & 63;
        int node = n0 + i;
        if (node < N) {
            int idx = node * DD + dpp;
            out[idx] = out[idx] + sp[i][dpp] + sp[i][64 + dpp] + bias[dpp];
        }
    }
}

// ---------------- launch ----------------------------------------------------
extern "C" void kernel_launch(void* const* d_in, const int* in_sizes, int n_in,
                              void* d_out, int out_size) {
    const float* x        = (const float*)d_in[0];
    const int*   ei       = (const int*)  d_in[1];
    const int*   eattr    = (const int*)  d_in[2];
    const float* W        = (const float*)d_in[3];
    const float* bW       = (const float*)d_in[4];
    const float* att      = (const float*)d_in[5];
    const float* bias     = (const float*)d_in[6];
    const float* bond_emb = (const float*)d_in[7];
    float* out = (float*)d_out;

    int N = in_sizes[0] / DD;
    int E = in_sizes[1] / 2;

    k_init<<<(N * 2 + 255) / 256, 256>>>(N);
    k_prep<<<126, 256>>>(W, bW, att, bond_emb);
    k_adot_hist<<<(E + 255) / 256, 256>>>(x, ei, N, E);
    k_scan1<<<SCAN_BLOCKS, 1024>>>(N);
    k_scan2<<<1, 64>>>();
    k_scan3<<<SCAN_BLOCKS, 1024>>>(N);
    k_softperm<<<(E + 255) / 256, 256>>>(ei, eattr, E);
    k_sinv<<<(N * 2 + 255) / 256, 256>>>(N);
    k_aggr<<<888, 256>>>(x, out, N);
    k_zgemm<<<(N + 15) / 16, 128>>>(W, bias, out, N);
}